// round 4
// baseline (speedup 1.0000x reference)
#include <cuda_runtime.h>

#define BSZ    512
#define NN     128
#define NMAT   2560
#define QS     40            // quarter stride (words): 40 ≡ 8  (mod 32)
#define RS     164           // row stride = 4*QS + 4:  164 ≡ 4 (mod 32)
#define VS     136           // replica stride for Rv/Cv: 136 ≡ 8 (mod 32)

// ---------------- persistent scratch (__device__ globals) -------------------
__device__ float g_Ts[128];          // sorted ReLU thresholds
__device__ int   g_perm[128];        // sort permutation
__device__ float g_A [129 * 128];    // per-interval slope table
__device__ float g_Cc[129 * 128];    // per-interval offset table (incl b2)
__device__ int   g_kidx[BSZ * NN];   // interval index per input scalar

// ---------------- kernel 1: rank thresholds (1 block) -----------------------
__global__ void k_rank(const float* __restrict__ w1, const float* __restrict__ b1)
{
    __shared__ float tsh[128];
    int l = threadIdx.x;
    float w  = w1[l];
    float bb = b1[l];
    float tv;
    if (w != 0.0f) tv = -bb / w;
    else           tv = (bb > 0.0f) ? -3.0e38f : 3.0e38f;
    tsh[l] = tv;
    __syncthreads();
    int r = 0;
    for (int p = 0; p < 128; ++p) {
        float o = tsh[p];
        r += (o < tv) || (o == tv && p < l);
    }
    g_Ts[r]   = tv;
    g_perm[r] = l;
}

// ---------------- kernel 2: interval tables A,C  [129 x 128] ----------------
__global__ void k_tables(const float* __restrict__ w1, const float* __restrict__ b1,
                         const float* __restrict__ w2, const float* __restrict__ b2)
{
    __shared__ float ws[128], bs[128];
    __shared__ int   ps[128];
    int k = blockIdx.x;       // 0..128
    int j = threadIdx.x;      // 0..127
    ps[j] = g_perm[j];
    __syncthreads();
    ws[j] = w1[ps[j]];
    bs[j] = b1[ps[j]];
    __syncthreads();
    float a = 0.f, c = 0.f;
    #pragma unroll 4
    for (int p = 0; p < 128; ++p) {
        float w  = ws[p];
        float bb = bs[p];
        bool pos = (w > 0.f) || (w == 0.f && bb > 0.f);
        bool act = pos ? (p < k) : (p >= k);
        if (act) {
            float wv = w2[j * 128 + ps[p]];
            a = fmaf(w,  wv, a);
            c = fmaf(bb, wv, c);
        }
    }
    g_A [k * 128 + j] = a;
    g_Cc[k * 128 + j] = c + b2[j];
}

// ---------------- kernel 3: interval index per scalar -----------------------
__global__ void k_kidx(const float* __restrict__ x)
{
    int i = blockIdx.x * blockDim.x + threadIdx.x;
    if (i >= BSZ * NN) return;
    float xv = x[i];
    int lo = 0, hi = 128;
    while (lo < hi) {
        int mid = (lo + hi) >> 1;
        if (g_Ts[mid] < xv) lo = mid + 1; else hi = mid;
    }
    g_kidx[i] = lo;
}

// ---------------- kernel 4: main Sinkhorn, 512 thr / matrix -----------------
// Matrix stored COLUMN-major in smem with XOR swizzle:
//   MT[j][i] = M0[i][j] at word  j*RS + (i>>5)*QS + ((i&31) ^ (8*((j>>5)&3)))
// Rv/Cv are kept in 4 replicas (stride VS=136): replica q is read by the
// quarter-q threads so each phase's four 16B regions hit distinct bank-quads.
__global__ __launch_bounds__(512, 2) void k_sinkhorn(
    const float* __restrict__ x,
    const float* __restrict__ noise,
    float* __restrict__ out)
{
    extern __shared__ float sm[];
    float* MT  = sm;                      // [128][RS]
    float* RvR = sm + 128 * RS;           // [4][VS]
    float* CvR = RvR + 4 * VS;            // [4][VS]

    const int m   = blockIdx.x;
    const int b   = m & (BSZ - 1);
    const int tid = threadIdx.x;
    const int r   = tid >> 2;             // row 0..127
    const int q   = tid & 3;              // quarter 0..3

    // init all 4 Cv replicas to 1
    for (int i = tid; i < 4 * VS; i += 512) CvR[i] = 1.0f;

    const float xv = x[b * NN + r];
    const int   kr = g_kidx[b * NN + r];

    // ---- prologue: this thread's row quarter  M0[r][32q .. 32q+31]
    const float* nz = noise + (size_t)m * (NN * NN) + r * NN + 32 * q;
    const float* Ar = g_A  + kr * 128 + 32 * q;
    const float* Cr = g_Cc + kr * 128 + 32 * q;

    float4 rr[8];
    #pragma unroll
    for (int p = 0; p < 8; ++p) {
        float4 a4 = *(const float4*)(Ar + 4 * p);
        float4 c4 = *(const float4*)(Cr + 4 * p);
        float4 n4 = *(const float4*)(nz + 4 * p);
        float4 e;
        e.x = __expf(fmaf(a4.x, xv, c4.x) + n4.x);
        e.y = __expf(fmaf(a4.y, xv, c4.y) + n4.y);
        e.z = __expf(fmaf(a4.z, xv, c4.z) + n4.z);
        e.w = __expf(fmaf(a4.w, xv, c4.w) + n4.w);
        rr[p] = e;
    }

    // ---- transposed store into MT (scalar, conflict-free via XOR swizzle)
    {
        const int pos_i = (r >> 5) * QS + ((r & 31) ^ (8 * q));
        const float* rrf = (const float*)rr;
        #pragma unroll
        for (int s = 0; s < 32; ++s) {
            int j = 32 * q + s;
            MT[j * RS + pos_i] = rrf[s];
        }
    }
    __syncthreads();

    // ---- Sinkhorn iterations: R = 1/(M0 C);  C = 1/(M0^T R)
    const int cb = r * RS + q * QS;        // this thread's MT row-quarter base
    const int xr = 8 * ((r >> 5) & 3);     // XOR swizzle for MT row r
    const float* myRv = RvR + q * VS + 32 * q;   // own quarter, own replica
    const float* myCv = CvR + q * VS + 32 * q;

    for (int it = 0; it < 10; ++it) {
        // row GEMV from registers, C broadcast from replicated smem
        float4 acc = make_float4(0.f, 0.f, 0.f, 0.f);
        #pragma unroll
        for (int p = 0; p < 8; ++p) {
            float4 c4 = *(const float4*)(myCv + 4 * p);
            acc.x = fmaf(rr[p].x, c4.x, acc.x);
            acc.y = fmaf(rr[p].y, c4.y, acc.y);
            acc.z = fmaf(rr[p].z, c4.z, acc.z);
            acc.w = fmaf(rr[p].w, c4.w, acc.w);
        }
        float s = (acc.x + acc.y) + (acc.z + acc.w);
        s += __shfl_xor_sync(0xffffffffu, s, 1);
        s += __shfl_xor_sync(0xffffffffu, s, 2);
        RvR[q * VS + r] = __fdividef(1.0f, s);   // each lane -> its replica
        __syncthreads();

        // col GEMV: vec4 reads of MT row r (logical column r of M0)
        float4 t4 = make_float4(0.f, 0.f, 0.f, 0.f);
        #pragma unroll
        for (int p = 0; p < 8; ++p) {
            int off = (4 * p) ^ xr;                      // swizzled MT offset
            float4 mv = *(const float4*)(MT + cb + off); // elems 32q+4p..+3
            float4 rv = *(const float4*)(myRv + 4 * p);  // matching, unswizzled
            t4.x = fmaf(mv.x, rv.x, t4.x);
            t4.y = fmaf(mv.y, rv.y, t4.y);
            t4.z = fmaf(mv.z, rv.z, t4.z);
            t4.w = fmaf(mv.w, rv.w, t4.w);
        }
        float t = (t4.x + t4.y) + (t4.z + t4.w);
        t += __shfl_xor_sync(0xffffffffu, t, 1);
        t += __shfl_xor_sync(0xffffffffu, t, 2);
        CvR[q * VS + r] = __fdividef(1.0f, t);
        __syncthreads();
    }

    // ---- epilogue: out[m][r][j] = MT[r][j] * Rv[j] * Cv[r]
    const float ca = CvR[r];               // replica 0, broadcast per row
    float* om = out + (size_t)m * (NN * NN) + r * NN + 32 * q;
    #pragma unroll
    for (int p = 0; p < 8; ++p) {
        int off = (4 * p) ^ xr;
        float4 mv = *(const float4*)(MT + cb + off);     // elems j=32q+4p..+3
        float4 rv = *(const float4*)(myRv + 4 * p);
        float4 o;
        o.x = mv.x * rv.x * ca;
        o.y = mv.y * rv.y * ca;
        o.z = mv.z * rv.z * ca;
        o.w = mv.w * rv.w * ca;
        *(float4*)(om + 4 * p) = o;                      // unswizzled store
    }
}

// ---------------- launch ----------------------------------------------------
extern "C" void kernel_launch(void* const* d_in, const int* in_sizes, int n_in,
                              void* d_out, int out_size)
{
    const float* x     = (const float*)d_in[0];
    const float* w1    = (const float*)d_in[1];
    const float* b1    = (const float*)d_in[2];
    const float* w2    = (const float*)d_in[3];
    const float* b2    = (const float*)d_in[4];
    const float* noise = (const float*)d_in[5];
    float* out = (float*)d_out;

    k_rank  <<<1,   128>>>(w1, b1);
    k_tables<<<129, 128>>>(w1, b1, w2, b2);
    k_kidx  <<<256, 256>>>(x);

    const int smem_bytes = (128 * RS + 8 * VS) * 4;   // 88,320 B
    cudaFuncSetAttribute(k_sinkhorn, cudaFuncAttributeMaxDynamicSharedMemorySize,
                         smem_bytes);
    k_sinkhorn<<<NMAT, 512, smem_bytes>>>(x, noise, out);
}

// round 5
// speedup vs baseline: 1.7348x; 1.7348x over previous
#include <cuda_runtime.h>

#define BSZ  512
#define NN   128
#define NMAT 2560
#define SS   132             // stage row stride (words): 132 ≡ 4 (mod 32)

// ---------------- persistent scratch (__device__ globals) -------------------
__device__ float g_Ts[128];
__device__ int   g_perm[128];
__device__ float g_A [129 * 128];
__device__ float g_Cc[129 * 128];
__device__ int   g_kidx[BSZ * NN];

// ---------------- kernel 1: rank thresholds ---------------------------------
__global__ void k_rank(const float* __restrict__ w1, const float* __restrict__ b1)
{
    __shared__ float tsh[128];
    int l = threadIdx.x;
    float w  = w1[l];
    float bb = b1[l];
    float tv;
    if (w != 0.0f) tv = -bb / w;
    else           tv = (bb > 0.0f) ? -3.0e38f : 3.0e38f;
    tsh[l] = tv;
    __syncthreads();
    int r = 0;
    for (int p = 0; p < 128; ++p) {
        float o = tsh[p];
        r += (o < tv) || (o == tv && p < l);
    }
    g_Ts[r]   = tv;
    g_perm[r] = l;
}

// ---------------- kernel 2: interval tables ---------------------------------
__global__ void k_tables(const float* __restrict__ w1, const float* __restrict__ b1,
                         const float* __restrict__ w2, const float* __restrict__ b2)
{
    __shared__ float ws[128], bs[128];
    __shared__ int   ps[128];
    int k = blockIdx.x;       // 0..128
    int j = threadIdx.x;      // 0..127
    ps[j] = g_perm[j];
    __syncthreads();
    ws[j] = w1[ps[j]];
    bs[j] = b1[ps[j]];
    __syncthreads();
    float a = 0.f, c = 0.f;
    #pragma unroll 4
    for (int p = 0; p < 128; ++p) {
        float w  = ws[p];
        float bb = bs[p];
        bool pos = (w > 0.f) || (w == 0.f && bb > 0.f);
        bool act = pos ? (p < k) : (p >= k);
        if (act) {
            float wv = w2[j * 128 + ps[p]];
            a = fmaf(w,  wv, a);
            c = fmaf(bb, wv, c);
        }
    }
    g_A [k * 128 + j] = a;
    g_Cc[k * 128 + j] = c + b2[j];
}

// ---------------- kernel 3: interval index per scalar -----------------------
__global__ void k_kidx(const float* __restrict__ x)
{
    int i = blockIdx.x * blockDim.x + threadIdx.x;
    if (i >= BSZ * NN) return;
    float xv = x[i];
    int lo = 0, hi = 128;
    while (lo < hi) {
        int mid = (lo + hi) >> 1;
        if (g_Ts[mid] < xv) lo = mid + 1; else hi = mid;
    }
    g_kidx[i] = lo;
}

// ---------------- kernel 4: register-resident Sinkhorn ----------------------
// warp w: g=w>>2 (row group), q=w&3 (column quarter, uniform per warp)
// lane i: row r=32g+i; thread holds M0[r][32q..32q+31] in rr[8] (float4)
__global__ __launch_bounds__(512, 2) void k_sinkhorn(
    const float* __restrict__ x,
    const float* __restrict__ noise,
    float* __restrict__ out)
{
    extern __shared__ float sm[];
    float* stage = sm;                    // [128][SS]  (prologue M0, epilogue out^T)
    float* P     = sm + 128 * SS;         // [4][SS]    cross-warp partials
    float* Rv    = P  + 4 * SS;           // [128]
    float* Cv    = Rv + 128;              // [128]
    float* xs    = Cv + 128;              // [128]
    int*   ks    = (int*)(xs + 128);      // [128]

    const int m    = blockIdx.x;
    const int b    = m & (BSZ - 1);
    const int tid  = threadIdx.x;
    const int lane = tid & 31;
    const int wrp  = tid >> 5;
    const int g    = wrp >> 2;
    const int q    = wrp & 3;
    const int r    = 32 * g + lane;

    if (tid < 128) {
        xs[tid] = x[b * NN + tid];
        ks[tid] = g_kidx[b * NN + tid];
        Cv[tid] = 1.0f;
    }
    __syncthreads();

    // ---- prologue: build M0 into stage[row][col], fully coalesced ----------
    const float* nzm = noise + (size_t)m * (NN * NN);
    #pragma unroll
    for (int h = 0; h < 8; ++h) {
        int id  = h * 512 + tid;          // float4 index; row uniform per warp
        int row = id >> 5;
        int c4  = (id & 31) * 4;
        int   kr = ks[row];               // warp-uniform broadcast
        float xv = xs[row];
        float4 a4 = *(const float4*)(g_A  + kr * 128 + c4);   // coalesced, L2-hot
        float4 q4 = *(const float4*)(g_Cc + kr * 128 + c4);
        float4 n4 = *(const float4*)(nzm + id * 4);           // coalesced
        float4 e;
        e.x = __expf(fmaf(a4.x, xv, q4.x) + n4.x);
        e.y = __expf(fmaf(a4.y, xv, q4.y) + n4.y);
        e.z = __expf(fmaf(a4.z, xv, q4.z) + n4.z);
        e.w = __expf(fmaf(a4.w, xv, q4.w) + n4.w);
        *(float4*)(stage + row * SS + c4) = e;                // conflict-free
    }
    __syncthreads();

    // ---- pick up own row quarter into registers ----------------------------
    float4 rr[8];
    #pragma unroll
    for (int p = 0; p < 8; ++p)
        rr[p] = *(const float4*)(stage + r * SS + 32 * q + 4 * p);  // 4i+4p banks: CF
    const float* af = (const float*)rr;

    // ---- Sinkhorn iterations ----------------------------------------------
    float R_own = 0.f;
    for (int it = 0; it < 10; ++it) {
        // row GEMV: dot(own slice, C) — C read as all-lane broadcast
        float4 acc = make_float4(0.f, 0.f, 0.f, 0.f);
        #pragma unroll
        for (int p = 0; p < 8; ++p) {
            float4 c4 = *(const float4*)(Cv + 32 * q + 4 * p);  // same addr all lanes
            acc.x = fmaf(rr[p].x, c4.x, acc.x);
            acc.y = fmaf(rr[p].y, c4.y, acc.y);
            acc.z = fmaf(rr[p].z, c4.z, acc.z);
            acc.w = fmaf(rr[p].w, c4.w, acc.w);
        }
        P[q * SS + r] = (acc.x + acc.y) + (acc.z + acc.w);      // CF scalar STS
        __syncthreads();
        if (tid < 128) {
            float t = P[tid] + P[SS + tid] + P[2 * SS + tid] + P[3 * SS + tid];
            Rv[tid] = __fdividef(1.0f, t);
        }
        __syncthreads();
        R_own = Rv[r];

        // col GEMV: butterfly over the warp's 32 rows, two 16-column passes.
        // After the passes, even lane L holds column 32q+cb+((L>>1)&15) partial.
        #pragma unroll
        for (int pass = 0; pass < 2; ++pass) {
            const int cb = 16 * pass;
            float w8[8];
            {   // stage off=16, x R folded in (col bit3 <- lane bit4)
                bool up = (lane & 16) != 0;
                #pragma unroll
                for (int j = 0; j < 8; ++j) {
                    float a_lo = af[cb + j];
                    float a_hi = af[cb + j + 8];
                    float send = (up ? a_lo : a_hi) * R_own;
                    float keep = (up ? a_hi : a_lo);
                    float recv = __shfl_xor_sync(0xffffffffu, send, 16);
                    w8[j] = fmaf(keep, R_own, recv);
                }
            }
            #pragma unroll
            for (int off = 8; off >= 2; off >>= 1) {   // col bit2..0 <- lane bit3..1
                int n = off >> 1;
                bool up = (lane & off) != 0;
                #pragma unroll
                for (int j = 0; j < n; ++j) {
                    float send = up ? w8[j] : w8[j + n];
                    float keep = up ? w8[j + n] : w8[j];
                    float recv = __shfl_xor_sync(0xffffffffu, send, off);
                    w8[j] = keep + recv;
                }
            }
            float v = w8[0] + __shfl_xor_sync(0xffffffffu, w8[0], 1);
            if ((lane & 1) == 0) {
                int c = cb + ((lane >> 1) & 15);
                P[g * SS + 32 * q + c] = v;             // 16 distinct banks: CF
            }
        }
        __syncthreads();
        if (tid < 128) {
            float t = P[tid] + P[SS + tid] + P[2 * SS + tid] + P[3 * SS + tid];
            Cv[tid] = __fdividef(1.0f, t);
        }
        __syncthreads();
    }

    // ---- epilogue: out[m][c][r] = M0[r][c]*R_r*C_c  (transpose via stage) --
    #pragma unroll
    for (int p = 0; p < 8; ++p) {
        float4 c4 = *(const float4*)(Cv + 32 * q + 4 * p);  // broadcast
        int cbase = 32 * q + 4 * p;
        float sx = rr[p].x * R_own, sy = rr[p].y * R_own;
        float sz = rr[p].z * R_own, sw = rr[p].w * R_own;
        stage[(cbase + 0) * SS + r] = sx * c4.x;            // CF scalar STS
        stage[(cbase + 1) * SS + r] = sy * c4.y;
        stage[(cbase + 2) * SS + r] = sz * c4.z;
        stage[(cbase + 3) * SS + r] = sw * c4.w;
    }
    __syncthreads();
    float* om = out + (size_t)m * (NN * NN);
    #pragma unroll
    for (int h = 0; h < 8; ++h) {
        int id  = h * 512 + tid;
        int row = id >> 5;
        int c4  = (id & 31) * 4;
        *(float4*)(om + id * 4) = *(const float4*)(stage + row * SS + c4);
    }
}

// ---------------- launch ----------------------------------------------------
extern "C" void kernel_launch(void* const* d_in, const int* in_sizes, int n_in,
                              void* d_out, int out_size)
{
    const float* x     = (const float*)d_in[0];
    const float* w1    = (const float*)d_in[1];
    const float* b1    = (const float*)d_in[2];
    const float* w2    = (const float*)d_in[3];
    const float* b2    = (const float*)d_in[4];
    const float* noise = (const float*)d_in[5];
    float* out = (float*)d_out;

    k_rank  <<<1,   128>>>(w1, b1);
    k_tables<<<129, 128>>>(w1, b1, w2, b2);
    k_kidx  <<<256, 256>>>(x);

    const int smem_bytes = (128 * SS + 4 * SS + 4 * 128) * 4;   // 71,744 B
    cudaFuncSetAttribute(k_sinkhorn, cudaFuncAttributeMaxDynamicSharedMemorySize,
                         smem_bytes);
    k_sinkhorn<<<NMAT, 512, smem_bytes>>>(x, noise, out);
}